// round 5
// baseline (speedup 1.0000x reference)
#include <cuda_runtime.h>

#define BB 256
#define TT 512
#define NT 128
#define GO_IDX 1
#define EOS_IDX 2
#define NEGV -10000.0f

// Scratch (allocation-free rule: __device__ globals)
__device__ float  g_alphas[BB * TT * NT];   // 64 MB alphas trajectory
__device__ float2 g_stats[BB * TT];         // per-(b,t) {rowmax, log(sum exp(u-rowmax))}
__device__ int    g_len[BB];                // normalized int32 lengths

// ---------------------------------------------------------------------------
// Kernel 0: normalize lengths dtype (int32 vs int64) + defensive clamp.
// ---------------------------------------------------------------------------
__global__ void lens_kernel(const int* __restrict__ lens32) {
    int b = threadIdx.x;                     // 256 threads, 1 block
    bool is64 = (lens32[1] == 0);
    int v = is64 ? lens32[2 * b] : lens32[b];
    g_len[b] = min(max(v, 1), TT);
}

// ---------------------------------------------------------------------------
// Kernel A: per-row logsumexp stats (bandwidth bound, ~67MB read)
// ---------------------------------------------------------------------------
__global__ void stats_kernel(const float* __restrict__ u) {
    int warp = blockIdx.x * (blockDim.x >> 5) + (threadIdx.x >> 5);
    int lane = threadIdx.x & 31;
    if (warp >= BB * TT) return;
    const float4* row = reinterpret_cast<const float4*>(u + (size_t)warp * NT);
    float4 v = row[lane];
    float m = fmaxf(fmaxf(v.x, v.y), fmaxf(v.z, v.w));
    #pragma unroll
    for (int o = 16; o; o >>= 1) m = fmaxf(m, __shfl_xor_sync(0xffffffffu, m, o));
    float s = expf(v.x - m) + expf(v.y - m) + expf(v.z - m) + expf(v.w - m);
    #pragma unroll
    for (int o = 16; o; o >>= 1) s += __shfl_xor_sync(0xffffffffu, s, o);
    if (lane == 0) g_stats[warp] = make_float2(m, logf(s));
}

// ---------------------------------------------------------------------------
// Kernel B: forward Viterbi. 2 batches per 128-thread block (grid=128 -> one
// block per SM, perfect SMSP balance; rt registers amortized over 2 batches).
// ---------------------------------------------------------------------------
__device__ __forceinline__ float vstep(const float4* __restrict__ a4,
                                       const float* __restrict__ rt,
                                       float uv, float2 s)
{
    float m0 = -3.4e38f, m1 = -3.4e38f, m2 = -3.4e38f, m3 = -3.4e38f;
    #pragma unroll
    for (int q = 0; q < NT / 4; q++) {
        float4 a = a4[q];
        m0 = fmaxf(m0, a.x + rt[4 * q + 0]);
        m1 = fmaxf(m1, a.y + rt[4 * q + 1]);
        m2 = fmaxf(m2, a.z + rt[4 * q + 2]);
        m3 = fmaxf(m3, a.w + rt[4 * q + 3]);
    }
    float m = fmaxf(fmaxf(m0, m1), fmaxf(m2, m3));
    // probv = (u - rowmax) - L  (matches reference's log_softmax arithmetic;
    // any ULP error in L is uniform across tags -> decisions invariant)
    return m + ((uv - s.x) - s.y);
}

__global__ __launch_bounds__(128) void forward_kernel(
    const float* __restrict__ u,
    const float* __restrict__ trans)
{
    int b0 = 2 * blockIdx.x, b1 = b0 + 1;
    int cur = threadIdx.x;

    // cache this tag's transition row in registers (128 regs)
    float rt[NT];
    #pragma unroll
    for (int p = 0; p < NT; p++) rt[p] = __ldg(trans + cur * NT + p);

    __shared__ __align__(16) float abuf[2][2][NT];   // [batch][parity][tag]
    float a_init = (cur == GO_IDX) ? 0.0f : NEGV;    // exact log_softmax of init
    abuf[0][0][cur] = a_init;
    abuf[1][0][cur] = a_init;

    int len0 = g_len[b0], len1 = g_len[b1];
    int lmax = max(len0, len1);
    const float*  ub0 = u + (size_t)b0 * TT * NT;
    const float*  ub1 = u + (size_t)b1 * TT * NT;
    const float2* st0 = g_stats + (size_t)b0 * TT;
    const float2* st1 = g_stats + (size_t)b1 * TT;
    float*        ao0 = g_alphas + (size_t)b0 * TT * NT;
    float*        ao1 = g_alphas + (size_t)b1 * TT * NT;
    __syncthreads();

    // 1-step software pipeline on uv / stats
    float  uv0 = ub0[cur],  uv1 = ub1[cur];
    float2 s0  = st0[0],    s1  = st1[0];

    for (int t = 0; t < lmax; t++) {
        float nuv0 = 0.0f, nuv1 = 0.0f;
        float2 ns0 = make_float2(0.f, 0.f), ns1 = ns0;
        if (t + 1 < len0) { nuv0 = ub0[(t + 1) * NT + cur]; ns0 = st0[t + 1]; }
        if (t + 1 < len1) { nuv1 = ub1[(t + 1) * NT + cur]; ns1 = st1[t + 1]; }

        bool w0 = t < len0, w1 = t < len1;
        float na0, na1;
        if (w0) na0 = vstep(reinterpret_cast<const float4*>(abuf[0][t & 1]), rt, uv0, s0);
        if (w1) na1 = vstep(reinterpret_cast<const float4*>(abuf[1][t & 1]), rt, uv1, s1);
        if (w0) { abuf[0][(t + 1) & 1][cur] = na0; ao0[t * NT + cur] = na0; }
        if (w1) { abuf[1][(t + 1) & 1][cur] = na1; ao1[t * NT + cur] = na1; }
        __syncthreads();
        uv0 = nuv0; s0 = ns0; uv1 = nuv1; s1 = ns1;
    }
}

// ---------------------------------------------------------------------------
// Kernel C: terminal argmax + backtrace (recompute backpointers). Warp/batch.
// Alphas prefetched in double-buffered chunks of 8 (MLP=8 covers DRAM lat);
// __ldcs streaming hint keeps the 64KB trans table L1-resident for the
// tag-dependent load on the serial chain.
// ---------------------------------------------------------------------------
__device__ __forceinline__ unsigned fmono(float f) {
    unsigned u = __float_as_uint(f);
    int s = ((int)u) >> 31;
    return u ^ (unsigned)(s | 0x80000000);
}
__device__ __forceinline__ float fmono_inv(unsigned m) {
    return (m & 0x80000000u) ? __uint_as_float(m & 0x7fffffffu)
                             : __uint_as_float(~m);
}

__global__ __launch_bounds__(32) void backtrace_kernel(
    const float* __restrict__ trans,
    float* __restrict__ out)
{
    int b = blockIdx.x;
    int lane = threadIdx.x;        // 32 threads
    int len = g_len[b];
    float* preds = out + (size_t)b * TT;

    // preds[t] = 0 for t >= len
    for (int t = len + lane; t < TT; t += 32) preds[t] = 0.0f;

    const float* ab = g_alphas + (size_t)b * TT * NT;

    // terminal: argmax_cur( alphas[len-1][cur] + trans[EOS][cur] ), first-max ties
    float4 a  = __ldcs(reinterpret_cast<const float4*>(ab + (size_t)(len - 1) * NT) + lane);
    float4 tv = __ldg(reinterpret_cast<const float4*>(trans + EOS_IDX * NT) + lane);
    unsigned c0 = fmono(a.x + tv.x), c1 = fmono(a.y + tv.y);
    unsigned c2 = fmono(a.z + tv.z), c3 = fmono(a.w + tv.w);
    unsigned best = max(max(c0, c1), max(c2, c3));
    unsigned wmax = __reduce_max_sync(0xffffffffu, best);
    unsigned idx = 0x7fffffffu;
    if (c3 == wmax) idx = 4u * lane + 3u;
    if (c2 == wmax) idx = 4u * lane + 2u;
    if (c1 == wmax) idx = 4u * lane + 1u;
    if (c0 == wmax) idx = 4u * lane + 0u;
    int tag = (int)__reduce_min_sync(0xffffffffu, idx);
    if (lane == 0) {
        out[(size_t)BB * TT + b] = fmono_inv(wmax);  // path score (exact max)
        preds[len - 1] = (float)tag;
    }

    // chase rows R_i = len-2-i for i in [0, nrows); chunked prefetch depth 8
    int nrows = len - 1;
    int nchunks = (nrows + 7) >> 3;
    float4 bufA[8], bufB[8];

#define BT_LOAD(DST, C)                                                        \
    {                                                                          \
        _Pragma("unroll")                                                      \
        for (int k = 0; k < 8; k++) {                                          \
            int i = 8 * (C) + k;                                               \
            if (i < nrows)                                                     \
                DST[k] = __ldcs(reinterpret_cast<const float4*>(               \
                             ab + (size_t)(len - 2 - i) * NT) + lane);         \
        }                                                                      \
    }

#define BT_PROC(SRC, C)                                                        \
    {                                                                          \
        _Pragma("unroll")                                                      \
        for (int k = 0; k < 8; k++) {                                          \
            int i = 8 * (C) + k;                                               \
            if (i >= nrows) break;                                             \
            float4 av = SRC[k];                                                \
            float4 tr = __ldg(reinterpret_cast<const float4*>(                 \
                                  trans + tag * NT) + lane);                   \
            c0 = fmono(av.x + tr.x); c1 = fmono(av.y + tr.y);                  \
            c2 = fmono(av.z + tr.z); c3 = fmono(av.w + tr.w);                  \
            best = max(max(c0, c1), max(c2, c3));                              \
            wmax = __reduce_max_sync(0xffffffffu, best);                       \
            idx = 0x7fffffffu;                                                 \
            if (c3 == wmax) idx = 4u * lane + 3u;                              \
            if (c2 == wmax) idx = 4u * lane + 2u;                              \
            if (c1 == wmax) idx = 4u * lane + 1u;                              \
            if (c0 == wmax) idx = 4u * lane + 0u;                              \
            tag = (int)__reduce_min_sync(0xffffffffu, idx);                    \
            if (lane == 0) preds[len - 2 - i] = (float)tag;                    \
        }                                                                      \
    }

    if (nchunks > 0) BT_LOAD(bufA, 0);
    for (int c = 0; c < nchunks; c++) {
        if ((c & 1) == 0) {
            if (c + 1 < nchunks) BT_LOAD(bufB, c + 1);
            BT_PROC(bufA, c);
        } else {
            if (c + 1 < nchunks) BT_LOAD(bufA, c + 1);
            BT_PROC(bufB, c);
        }
    }
#undef BT_LOAD
#undef BT_PROC
}

// ---------------------------------------------------------------------------
extern "C" void kernel_launch(void* const* d_in, const int* in_sizes, int n_in,
                              void* d_out, int out_size)
{
    const float* u     = (const float*)d_in[0];   // unaries [B,T,N] f32
    const float* trans = (const float*)d_in[1];   // trans  [1,N,N] f32
    const int*   lens  = (const int*)d_in[2];     // lengths [B] (i32 or i64, detected)
    float* out = (float*)d_out;                   // [B*T preds | B scores]

    lens_kernel<<<1, BB>>>(lens);
    stats_kernel<<<(BB * TT) / 8, 256>>>(u);
    forward_kernel<<<BB / 2, 128>>>(u, trans);
    backtrace_kernel<<<BB, 32>>>(trans, out);
}

// round 8
// speedup vs baseline: 1.2823x; 1.2823x over previous
#include <cuda_runtime.h>

#define BB 256
#define TT 512
#define NT 128
#define GO_IDX 1
#define EOS_IDX 2
#define NEGV -10000.0f

// Scratch (allocation-free rule: __device__ globals)
__device__ float  g_alphas[BB * TT * NT];   // 64 MB alphas trajectory
__device__ float2 g_stats[BB * TT];         // per-(b,t) {rowmax, log(sum exp(u-rowmax))}
__device__ int    g_len[BB];                // normalized int32 lengths

// ---------------------------------------------------------------------------
// Kernel 0: normalize lengths dtype (int32 vs int64) + defensive clamp.
// ---------------------------------------------------------------------------
__global__ void lens_kernel(const int* __restrict__ lens32) {
    int b = threadIdx.x;                     // 256 threads, 1 block
    bool is64 = (lens32[1] == 0);
    int v = is64 ? lens32[2 * b] : lens32[b];
    g_len[b] = min(max(v, 1), TT);
}

// ---------------------------------------------------------------------------
// Kernel A: per-row logsumexp stats (bandwidth bound, ~67MB read)
// ---------------------------------------------------------------------------
__global__ void stats_kernel(const float* __restrict__ u) {
    int warp = blockIdx.x * (blockDim.x >> 5) + (threadIdx.x >> 5);
    int lane = threadIdx.x & 31;
    if (warp >= BB * TT) return;
    const float4* row = reinterpret_cast<const float4*>(u + (size_t)warp * NT);
    float4 v = row[lane];
    float m = fmaxf(fmaxf(v.x, v.y), fmaxf(v.z, v.w));
    #pragma unroll
    for (int o = 16; o; o >>= 1) m = fmaxf(m, __shfl_xor_sync(0xffffffffu, m, o));
    float s = expf(v.x - m) + expf(v.y - m) + expf(v.z - m) + expf(v.w - m);
    #pragma unroll
    for (int o = 16; o; o >>= 1) s += __shfl_xor_sync(0xffffffffu, s, o);
    if (lane == 0) g_stats[warp] = make_float2(m, logf(s));
}

// ---------------------------------------------------------------------------
// Kernel B: forward Viterbi recurrence (R4-proven form). 1 block per batch,
// 1 thread per tag. trans row in registers; alphas double-buffered in smem.
// ---------------------------------------------------------------------------
__global__ __launch_bounds__(128) void forward_kernel(
    const float* __restrict__ u,
    const float* __restrict__ trans)
{
    int b = blockIdx.x;
    int cur = threadIdx.x;

    // cache this tag's transition row in registers (128 regs)
    float rt[NT];
    #pragma unroll
    for (int p = 0; p < NT; p++) rt[p] = __ldg(trans + cur * NT + p);

    __shared__ __align__(16) float abuf[2][NT];
    abuf[0][cur] = (cur == GO_IDX) ? 0.0f : NEGV;   // exact log_softmax of init

    int len = g_len[b];
    const float*  ub = u + (size_t)b * TT * NT;
    const float2* st = g_stats + (size_t)b * TT;
    float*        ao = g_alphas + (size_t)b * TT * NT;
    __syncthreads();

    for (int t = 0; t < len; t++) {
        float  uv = ub[t * NT + cur];   // issued early; consumed after the loop
        float2 s  = st[t];
        const float4* a4 = reinterpret_cast<const float4*>(abuf[t & 1]);
        float m0 = -3.4e38f, m1 = -3.4e38f, m2 = -3.4e38f, m3 = -3.4e38f;
        #pragma unroll
        for (int q = 0; q < NT / 4; q++) {
            float4 a = a4[q];
            m0 = fmaxf(m0, a.x + rt[4 * q + 0]);
            m1 = fmaxf(m1, a.y + rt[4 * q + 1]);
            m2 = fmaxf(m2, a.z + rt[4 * q + 2]);
            m3 = fmaxf(m3, a.w + rt[4 * q + 3]);
        }
        float m = fmaxf(fmaxf(m0, m1), fmaxf(m2, m3));
        // probv = (u - rowmax) - L  (matches reference's log_softmax arithmetic;
        // any ULP error in L is uniform across tags -> decisions invariant)
        float na = m + ((uv - s.x) - s.y);
        abuf[(t + 1) & 1][cur] = na;
        ao[t * NT + cur] = na;
        __syncthreads();
    }
}

// ---------------------------------------------------------------------------
// Kernel C: terminal argmax + backtrace. 128 threads/block: warps 0-3
// pre-touch the 64KB trans table into L1 (per-launch-cold) and zero-fill
// preds; warp 0 then runs the serial chain with L1-resident trans (~39cyc)
// and chunked MLP=8 double-buffered alphas prefetch via __ldcs (evict-first,
// protects trans in L1).
// ---------------------------------------------------------------------------
__device__ __forceinline__ unsigned fmono(float f) {
    unsigned u = __float_as_uint(f);
    int s = ((int)u) >> 31;
    return u ^ (unsigned)(s | 0x80000000);
}
__device__ __forceinline__ float fmono_inv(unsigned m) {
    return (m & 0x80000000u) ? __uint_as_float(m & 0x7fffffffu)
                             : __uint_as_float(~m);
}

__global__ __launch_bounds__(128) void backtrace_kernel(
    const float* __restrict__ trans,
    float* __restrict__ out)
{
    int b = blockIdx.x;
    int tid = threadIdx.x;
    int len = g_len[b];
    float* preds = out + (size_t)b * TT;

    // preds[t] = 0 for t >= len (all 4 warps)
    for (int t = len + tid; t < TT; t += 128) preds[t] = 0.0f;

    // Pre-touch trans into L1 (64KB = 4096 float4; 32 float4 per thread).
    const float4* t4 = reinterpret_cast<const float4*>(trans);
    float acc = 0.0f;
    #pragma unroll
    for (int i = 0; i < (NT * NT / 4) / 128; i++) {
        float4 v = __ldg(t4 + tid + i * 128);
        acc += v.x + v.y + v.z + v.w;
    }
    // Unremovable, never-taken sink (acc is data-dependent).
    if (acc == -1.2345678e-33f && tid == 1023) preds[0] = acc;

    if (tid >= 32) return;   // warps 1-3 done (no further __syncthreads)
    int lane = tid;

    const float* ab = g_alphas + (size_t)b * TT * NT;

    // terminal: argmax_cur( alphas[len-1][cur] + trans[EOS][cur] ), first-max ties
    float4 a  = __ldcs(reinterpret_cast<const float4*>(ab + (size_t)(len - 1) * NT) + lane);
    float4 tv = __ldg(reinterpret_cast<const float4*>(trans + EOS_IDX * NT) + lane);
    unsigned c0 = fmono(a.x + tv.x), c1 = fmono(a.y + tv.y);
    unsigned c2 = fmono(a.z + tv.z), c3 = fmono(a.w + tv.w);
    unsigned best = max(max(c0, c1), max(c2, c3));
    unsigned wmax = __reduce_max_sync(0xffffffffu, best);
    unsigned idx = 0x7fffffffu;
    if (c3 == wmax) idx = 4u * lane + 3u;
    if (c2 == wmax) idx = 4u * lane + 2u;
    if (c1 == wmax) idx = 4u * lane + 1u;
    if (c0 == wmax) idx = 4u * lane + 0u;
    int tag = (int)__reduce_min_sync(0xffffffffu, idx);
    if (lane == 0) {
        out[(size_t)BB * TT + b] = fmono_inv(wmax);  // path score (exact max)
        preds[len - 1] = (float)tag;
    }

    // chase rows R_i = len-2-i for i in [0, nrows); chunked prefetch depth 8
    int nrows = len - 1;
    int nchunks = (nrows + 7) >> 3;
    float4 bufA[8], bufB[8];

#define BT_LOAD(DST, C)                                                        \
    {                                                                          \
        _Pragma("unroll")                                                      \
        for (int k = 0; k < 8; k++) {                                          \
            int i = 8 * (C) + k;                                               \
            if (i < nrows)                                                     \
                DST[k] = __ldcs(reinterpret_cast<const float4*>(               \
                             ab + (size_t)(len - 2 - i) * NT) + lane);         \
        }                                                                      \
    }

#define BT_PROC(SRC, C)                                                        \
    {                                                                          \
        _Pragma("unroll")                                                      \
        for (int k = 0; k < 8; k++) {                                          \
            int i = 8 * (C) + k;                                               \
            if (i >= nrows) break;                                             \
            float4 av = SRC[k];                                                \
            float4 tr = __ldg(reinterpret_cast<const float4*>(                 \
                                  trans + tag * NT) + lane);                   \
            c0 = fmono(av.x + tr.x); c1 = fmono(av.y + tr.y);                  \
            c2 = fmono(av.z + tr.z); c3 = fmono(av.w + tr.w);                  \
            best = max(max(c0, c1), max(c2, c3));                              \
            wmax = __reduce_max_sync(0xffffffffu, best);                       \
            idx = 0x7fffffffu;                                                 \
            if (c3 == wmax) idx = 4u * lane + 3u;                              \
            if (c2 == wmax) idx = 4u * lane + 2u;                              \
            if (c1 == wmax) idx = 4u * lane + 1u;                              \
            if (c0 == wmax) idx = 4u * lane + 0u;                              \
            tag = (int)__reduce_min_sync(0xffffffffu, idx);                    \
            if (lane == 0) preds[len - 2 - i] = (float)tag;                    \
        }                                                                      \
    }

    if (nchunks > 0) BT_LOAD(bufA, 0);
    for (int c = 0; c < nchunks; c++) {
        if ((c & 1) == 0) {
            if (c + 1 < nchunks) BT_LOAD(bufB, c + 1);
            BT_PROC(bufA, c);
        } else {
            if (c + 1 < nchunks) BT_LOAD(bufA, c + 1);
            BT_PROC(bufB, c);
        }
    }
#undef BT_LOAD
#undef BT_PROC
}

// ---------------------------------------------------------------------------
extern "C" void kernel_launch(void* const* d_in, const int* in_sizes, int n_in,
                              void* d_out, int out_size)
{
    const float* u     = (const float*)d_in[0];   // unaries [B,T,N] f32
    const float* trans = (const float*)d_in[1];   // trans  [1,N,N] f32
    const int*   lens  = (const int*)d_in[2];     // lengths [B] (i32 or i64, detected)
    float* out = (float*)d_out;                   // [B*T preds | B scores]

    lens_kernel<<<1, BB>>>(lens);
    stats_kernel<<<(BB * TT) / 8, 256>>>(u);
    forward_kernel<<<BB, 128>>>(u, trans);
    backtrace_kernel<<<BB, 128>>>(trans, out);
}

// round 9
// speedup vs baseline: 1.3167x; 1.0269x over previous
#include <cuda_runtime.h>

#define BB 256
#define TT 512
#define NT 128
#define GO_IDX 1
#define EOS_IDX 2
#define NEGV -10000.0f

// Scratch (allocation-free rule: __device__ globals)
__device__ float  g_alphas[BB * TT * NT];   // 64 MB alphas trajectory
__device__ float2 g_stats[BB * TT];         // per-(b,t) {rowmax, log(sum exp(u-rowmax))}
__device__ int    g_len[BB];                // normalized int32 lengths

// Packed fp32x2 helpers (B300 FADD2)
#define ADDX2(out, a, b) \
    asm("add.rn.f32x2 %0, %1, %2;" : "=l"(out) : "l"(a), "l"(b))
#define UNPK(lo, hi, v) \
    asm("mov.b64 {%0, %1}, %2;" : "=f"(lo), "=f"(hi) : "l"(v))
#define PK(out, lo, hi) \
    asm("mov.b64 %0, {%1, %2};" : "=l"(out) : "f"(lo), "f"(hi))

// ---------------------------------------------------------------------------
// Kernel 0: normalize lengths dtype (int32 vs int64) + defensive clamp.
// ---------------------------------------------------------------------------
__global__ void lens_kernel(const int* __restrict__ lens32) {
    int b = threadIdx.x;                     // 256 threads, 1 block
    bool is64 = (lens32[1] == 0);
    int v = is64 ? lens32[2 * b] : lens32[b];
    g_len[b] = min(max(v, 1), TT);
}

// ---------------------------------------------------------------------------
// Kernel A: per-row logsumexp stats (bandwidth bound, ~67MB read)
// ---------------------------------------------------------------------------
__global__ void stats_kernel(const float* __restrict__ u) {
    int warp = blockIdx.x * (blockDim.x >> 5) + (threadIdx.x >> 5);
    int lane = threadIdx.x & 31;
    if (warp >= BB * TT) return;
    const float4* row = reinterpret_cast<const float4*>(u + (size_t)warp * NT);
    float4 v = row[lane];
    float m = fmaxf(fmaxf(v.x, v.y), fmaxf(v.z, v.w));
    #pragma unroll
    for (int o = 16; o; o >>= 1) m = fmaxf(m, __shfl_xor_sync(0xffffffffu, m, o));
    float s = expf(v.x - m) + expf(v.y - m) + expf(v.z - m) + expf(v.w - m);
    #pragma unroll
    for (int o = 16; o; o >>= 1) s += __shfl_xor_sync(0xffffffffu, s, o);
    if (lane == 0) g_stats[warp] = make_float2(m, logf(s));
}

// ---------------------------------------------------------------------------
// Kernel B: forward Viterbi. 1 block per batch, 1 thread per tag.
// trans row PRE-PACKED as fp32x2 pairs in registers; packed add.rn.f32x2
// halves the FADD issue count (7 instr / 4 elems vs 9). Alphas double-
// buffered in smem; uv/stats prefetched 1 step ahead (clamped, in-bounds).
// ---------------------------------------------------------------------------
__global__ __launch_bounds__(128) void forward_kernel(
    const float* __restrict__ u,
    const float* __restrict__ trans)
{
    int b = blockIdx.x;
    int cur = threadIdx.x;

    // pack this tag's transition row into 64 fp32x2 register pairs
    unsigned long long rt2[NT / 2];
    const float2* tr2 = reinterpret_cast<const float2*>(trans + cur * NT);
    #pragma unroll
    for (int j = 0; j < NT / 2; j++) {
        float2 v = __ldg(tr2 + j);
        PK(rt2[j], v.x, v.y);
    }

    __shared__ __align__(16) float abuf[2][NT];
    abuf[0][cur] = (cur == GO_IDX) ? 0.0f : NEGV;   // exact log_softmax of init

    int len = g_len[b];
    const float*  ub = u + (size_t)b * TT * NT;
    const float2* st = g_stats + (size_t)b * TT;
    float*        ao = g_alphas + (size_t)b * TT * NT;
    __syncthreads();

    float  uv = ub[cur];
    float2 s  = st[0];

    for (int t = 0; t < len; t++) {
        // prefetch next step (clamped index -> always in-bounds, no predication)
        int tn = (t + 1 < len) ? (t + 1) : t;
        float  nuv = ub[tn * NT + cur];
        float2 ns  = st[tn];

        const ulonglong2* a2 = reinterpret_cast<const ulonglong2*>(abuf[t & 1]);
        float m0 = -3.4e38f, m1 = -3.4e38f, m2 = -3.4e38f, m3 = -3.4e38f;
        #pragma unroll
        for (int q = 0; q < NT / 4; q++) {
            ulonglong2 p = a2[q];            // LDS.128 broadcast
            unsigned long long s0, s1;
            ADDX2(s0, p.x, rt2[2 * q]);      // 2 adds in 1 issue
            ADDX2(s1, p.y, rt2[2 * q + 1]);
            float f0, f1, f2, f3;
            UNPK(f0, f1, s0);                // register renames
            UNPK(f2, f3, s1);
            m0 = fmaxf(m0, f0);
            m1 = fmaxf(m1, f1);
            m2 = fmaxf(m2, f2);
            m3 = fmaxf(m3, f3);
        }
        float m = fmaxf(fmaxf(m0, m1), fmaxf(m2, m3));
        // probv = (u - rowmax) - L  (matches reference log_softmax arithmetic;
        // ULP error in L is uniform across tags -> decisions invariant)
        float na = m + ((uv - s.x) - s.y);
        abuf[(t + 1) & 1][cur] = na;
        ao[t * NT + cur] = na;
        __syncthreads();
        uv = nuv; s = ns;
    }
}

// ---------------------------------------------------------------------------
// Kernel C: terminal argmax + backtrace. trans table copied to 64KB dynamic
// smem (unevictable, LDS=29cyc on the serial chain — L1 pre-touch proved
// useless in R8: tag-dependent loads were hitting L2 ~262cyc). Warp 0 runs
// the chain with chunked MLP=8 double-buffered __ldcs alphas prefetch.
// ---------------------------------------------------------------------------
__device__ __forceinline__ unsigned fmono(float f) {
    unsigned u = __float_as_uint(f);
    int s = ((int)u) >> 31;
    return u ^ (unsigned)(s | 0x80000000);
}
__device__ __forceinline__ float fmono_inv(unsigned m) {
    return (m & 0x80000000u) ? __uint_as_float(m & 0x7fffffffu)
                             : __uint_as_float(~m);
}

__global__ __launch_bounds__(128) void backtrace_kernel(
    const float* __restrict__ trans,
    float* __restrict__ out)
{
    extern __shared__ __align__(16) float strans[];   // 64KB: full trans table
    int b = blockIdx.x;
    int tid = threadIdx.x;
    int len = g_len[b];
    float* preds = out + (size_t)b * TT;

    // cooperative copy trans -> smem (4096 float4, 32 per thread)
    const float4* t4 = reinterpret_cast<const float4*>(trans);
    float4* s4 = reinterpret_cast<float4*>(strans);
    #pragma unroll
    for (int i = 0; i < (NT * NT / 4) / 128; i++)
        s4[tid + i * 128] = __ldg(t4 + tid + i * 128);

    // preds[t] = 0 for t >= len
    for (int t = len + tid; t < TT; t += 128) preds[t] = 0.0f;
    __syncthreads();

    if (tid >= 32) return;   // warps 1-3 done
    int lane = tid;

    const float* ab = g_alphas + (size_t)b * TT * NT;

    // terminal: argmax_cur( alphas[len-1][cur] + trans[EOS][cur] ), first-max ties
    float4 a  = __ldcs(reinterpret_cast<const float4*>(ab + (size_t)(len - 1) * NT) + lane);
    float4 tv = reinterpret_cast<const float4*>(strans + EOS_IDX * NT)[lane];
    unsigned c0 = fmono(a.x + tv.x), c1 = fmono(a.y + tv.y);
    unsigned c2 = fmono(a.z + tv.z), c3 = fmono(a.w + tv.w);
    unsigned best = max(max(c0, c1), max(c2, c3));
    unsigned wmax = __reduce_max_sync(0xffffffffu, best);
    unsigned idx = 0x7fffffffu;
    if (c3 == wmax) idx = 4u * lane + 3u;
    if (c2 == wmax) idx = 4u * lane + 2u;
    if (c1 == wmax) idx = 4u * lane + 1u;
    if (c0 == wmax) idx = 4u * lane + 0u;
    int tag = (int)__reduce_min_sync(0xffffffffu, idx);
    if (lane == 0) {
        out[(size_t)BB * TT + b] = fmono_inv(wmax);  // path score (exact max)
        preds[len - 1] = (float)tag;
    }

    // chase rows R_i = len-2-i for i in [0, nrows); chunked prefetch depth 8
    int nrows = len - 1;
    int nchunks = (nrows + 7) >> 3;
    float4 bufA[8], bufB[8];

#define BT_LOAD(DST, C)                                                        \
    {                                                                          \
        _Pragma("unroll")                                                      \
        for (int k = 0; k < 8; k++) {                                          \
            int i = 8 * (C) + k;                                               \
            if (i < nrows)                                                     \
                DST[k] = __ldcs(reinterpret_cast<const float4*>(               \
                             ab + (size_t)(len - 2 - i) * NT) + lane);         \
        }                                                                      \
    }

#define BT_PROC(SRC, C)                                                        \
    {                                                                          \
        _Pragma("unroll")                                                      \
        for (int k = 0; k < 8; k++) {                                          \
            int i = 8 * (C) + k;                                               \
            if (i >= nrows) break;                                             \
            float4 av = SRC[k];                                                \
            float4 tr = reinterpret_cast<const float4*>(                       \
                            strans + tag * NT)[lane];                          \
            c0 = fmono(av.x + tr.x); c1 = fmono(av.y + tr.y);                  \
            c2 = fmono(av.z + tr.z); c3 = fmono(av.w + tr.w);                  \
            best = max(max(c0, c1), max(c2, c3));                              \
            wmax = __reduce_max_sync(0xffffffffu, best);                       \
            idx = 0x7fffffffu;                                                 \
            if (c3 == wmax) idx = 4u * lane + 3u;                              \
            if (c2 == wmax) idx = 4u * lane + 2u;                              \
            if (c1 == wmax) idx = 4u * lane + 1u;                              \
            if (c0 == wmax) idx = 4u * lane + 0u;                              \
            tag = (int)__reduce_min_sync(0xffffffffu, idx);                    \
            if (lane == 0) preds[len - 2 - i] = (float)tag;                    \
        }                                                                      \
    }

    if (nchunks > 0) BT_LOAD(bufA, 0);
    for (int c = 0; c < nchunks; c++) {
        if ((c & 1) == 0) {
            if (c + 1 < nchunks) BT_LOAD(bufB, c + 1);
            BT_PROC(bufA, c);
        } else {
            if (c + 1 < nchunks) BT_LOAD(bufA, c + 1);
            BT_PROC(bufB, c);
        }
    }
#undef BT_LOAD
#undef BT_PROC
}

// ---------------------------------------------------------------------------
extern "C" void kernel_launch(void* const* d_in, const int* in_sizes, int n_in,
                              void* d_out, int out_size)
{
    const float* u     = (const float*)d_in[0];   // unaries [B,T,N] f32
    const float* trans = (const float*)d_in[1];   // trans  [1,N,N] f32
    const int*   lens  = (const int*)d_in[2];     // lengths [B] (i32 or i64, detected)
    float* out = (float*)d_out;                   // [B*T preds | B scores]

    // 64KB dynamic smem for the trans table (idempotent attribute set; not an
    // allocation and not a stream op — safe under graph capture)
    cudaFuncSetAttribute(backtrace_kernel,
                         cudaFuncAttributeMaxDynamicSharedMemorySize,
                         NT * NT * (int)sizeof(float));

    lens_kernel<<<1, BB>>>(lens);
    stats_kernel<<<(BB * TT) / 8, 256>>>(u);
    forward_kernel<<<BB, 128>>>(u, trans);
    backtrace_kernel<<<BB, 128, NT * NT * sizeof(float)>>>(trans, out);
}